// round 6
// baseline (speedup 1.0000x reference)
#include <cuda_runtime.h>

#define T_DATA 20000
#define E_NO   2000
#define I_NO   500
#define SUBN   12
#define KEFF   64          // kernel support truncation: tail < 1e-10 (tau_max = e ~ 2.72)

typedef unsigned long long u64;

// ---------------- device scratch (allocation-free rule: __device__ globals) ----------------
__device__ float g_INe[SUBN][T_DATA];       // S_e @ C_e.T, transposed [s][t]
__device__ float g_INi[SUBN][T_DATA];
__device__ float g_syn_s[SUBN][T_DATA];     // causal-conv outputs, [s][t]
__device__ float g_syn_ns[SUBN][T_DATA];
__device__ float g_ker[4][SUBN][KEFF];      // 0: s_e  1: s_i  2: ns_e  3: ns_i

__device__ __forceinline__ float sigm(float x) {
    return __fdividef(1.0f, 1.0f + __expf(-x));
}

// packed 2xfp32 FMA (FFMA2) — PTX-only, pairs ride along the e-dimension for free
__device__ __forceinline__ u64 fma2(u64 a, u64 b, u64 acc) {
    asm("fma.rn.f32x2 %0, %1, %2, %0;" : "+l"(acc) : "l"(a), "l"(b));
    return acc;
}
__device__ __forceinline__ float f2sum(u64 v) {
    float lo = __uint_as_float((unsigned)(v & 0xffffffffull));
    float hi = __uint_as_float((unsigned)(v >> 32));
    return lo + hi;
}

// ---------------- kernel 1: synaptic basis kernels ----------------
// kern[s,c,k] = sum_b W[s,b,c] * tt * exp(-tt),  tt = max(k - exp(Delta[s,c]),0)/tau_b,
// tau_b = exp(0.5*b)
__global__ void basis_kernel(const float* __restrict__ Ws, const float* __restrict__ Wns,
                             const float* __restrict__ Ds, const float* __restrict__ Dns) {
    int n = blockIdx.x * blockDim.x + threadIdx.x;
    if (n >= 4 * SUBN * KEFF) return;
    int k = n % KEFF;
    int s = (n / KEFF) % SUBN;
    int q = n / (KEFF * SUBN);          // 0:s_e 1:s_i 2:ns_e 3:ns_i
    int c = q & 1;
    const float* W = (q >= 2) ? Wns : Ws;   // [12][3][2]
    const float* D = (q >= 2) ? Dns : Ds;   // [12][2]
    float d  = __expf(D[s * 2 + c]);
    float ts = fmaxf((float)k - d, 0.0f);
    float acc = 0.0f;
#pragma unroll
    for (int b = 0; b < 3; b++) {
        float tau = __expf(0.5f * (float)b);
        float tt  = ts / tau;
        acc += W[s * 6 + b * 2 + c] * tt * __expf(-tt);
    }
    g_ker[q][s][k] = acc;
}

// ---------------- kernel 2: skinny GEMM  IN[s][t] = sum_e S[t][e] * C[s][e] ----------------
// C staged in smem as 16B vectors (12x512 for E, 12x128 for I, zero padded).
// Each warp owns a batch of 4 time rows; lanes sweep E in 16B slices, accumulating
// packed f32x2 partial sums (even/odd e) with FFMA2; butterfly-reduce at the end.
#define TB 4
#define NTASK (T_DATA / TB)   // 5000

__global__ void __launch_bounds__(256, 1)
gemm_kernel(const ulonglong2* __restrict__ Se, const ulonglong2* __restrict__ Si,
            const ulonglong2* __restrict__ Ce, const ulonglong2* __restrict__ Ci) {
    extern __shared__ ulonglong2 sm4[];
    ulonglong2* Ce4 = sm4;            // [12][512]
    ulonglong2* Ci4 = sm4 + 12 * 512; // [12][128]
    int tid = threadIdx.x;
    for (int n = tid; n < 12 * 512; n += 256) {
        int s = n >> 9, q = n & 511;
        ulonglong2 v; v.x = 0ull; v.y = 0ull;
        if (q < 500) v = Ce[s * 500 + q];
        Ce4[n] = v;
    }
    for (int n = tid; n < 12 * 128; n += 256) {
        int s = n >> 7, q = n & 127;
        ulonglong2 v; v.x = 0ull; v.y = 0ull;
        if (q < 125) v = Ci[s * 125 + q];
        Ci4[n] = v;
    }
    __syncthreads();

    int lane = tid & 31;
    int gw   = blockIdx.x * 8 + (tid >> 5);
    int nw   = gridDim.x * 8;

    for (int task = gw; task < NTASK; task += nw) {
        int t0 = task * TB;
        u64 acc[TB][12];

        // ---------- phase E ----------
#pragma unroll
        for (int tb = 0; tb < TB; tb++)
#pragma unroll
            for (int s = 0; s < 12; s++) acc[tb][s] = 0ull;

#pragma unroll 1
        for (int sl = 0; sl < 16; sl++) {
            int e4 = (sl << 5) + lane;
            bool ok = (e4 < 500);
            ulonglong2 av[TB];
#pragma unroll
            for (int tb = 0; tb < TB; tb++) {
                ulonglong2 v; v.x = 0ull; v.y = 0ull;
                if (ok) v = Se[(t0 + tb) * 500 + e4];
                av[tb] = v;
            }
#pragma unroll
            for (int s = 0; s < 12; s++) {
                ulonglong2 c = Ce4[(s << 9) + e4];
#pragma unroll
                for (int tb = 0; tb < TB; tb++) {
                    u64 a = fma2(av[tb].x, c.x, acc[tb][s]);
                    acc[tb][s] = fma2(av[tb].y, c.y, a);
                }
            }
        }
#pragma unroll
        for (int tb = 0; tb < TB; tb++)
#pragma unroll
            for (int s = 0; s < 12; s++) {
                float v = f2sum(acc[tb][s]);
                v += __shfl_xor_sync(0xffffffffu, v, 16);
                v += __shfl_xor_sync(0xffffffffu, v, 8);
                v += __shfl_xor_sync(0xffffffffu, v, 4);
                v += __shfl_xor_sync(0xffffffffu, v, 2);
                v += __shfl_xor_sync(0xffffffffu, v, 1);
                if (lane == s) g_INe[s][t0 + tb] = v;
            }

        // ---------- phase I ----------
#pragma unroll
        for (int tb = 0; tb < TB; tb++)
#pragma unroll
            for (int s = 0; s < 12; s++) acc[tb][s] = 0ull;

#pragma unroll 1
        for (int sl = 0; sl < 4; sl++) {
            int e4 = (sl << 5) + lane;
            bool ok = (e4 < 125);
            ulonglong2 av[TB];
#pragma unroll
            for (int tb = 0; tb < TB; tb++) {
                ulonglong2 v; v.x = 0ull; v.y = 0ull;
                if (ok) v = Si[(t0 + tb) * 125 + e4];
                av[tb] = v;
            }
#pragma unroll
            for (int s = 0; s < 12; s++) {
                ulonglong2 c = Ci4[(s << 7) + e4];
#pragma unroll
                for (int tb = 0; tb < TB; tb++) {
                    u64 a = fma2(av[tb].x, c.x, acc[tb][s]);
                    acc[tb][s] = fma2(av[tb].y, c.y, a);
                }
            }
        }
#pragma unroll
        for (int tb = 0; tb < TB; tb++)
#pragma unroll
            for (int s = 0; s < 12; s++) {
                float v = f2sum(acc[tb][s]);
                v += __shfl_xor_sync(0xffffffffu, v, 16);
                v += __shfl_xor_sync(0xffffffffu, v, 8);
                v += __shfl_xor_sync(0xffffffffu, v, 4);
                v += __shfl_xor_sync(0xffffffffu, v, 2);
                v += __shfl_xor_sync(0xffffffffu, v, 1);
                if (lane == s) g_INi[s][t0 + tb] = v;
            }
    }
}

// ---------------- kernel 3: causal conv (per subunit, shared e/i inputs) ----------------
#define CONV_CHUNK 1024
__global__ void __launch_bounds__(256)
conv_kernel() {
    __shared__ float se_sm[CONV_CHUNK + KEFF];
    __shared__ float si_sm[CONV_CHUNK + KEFF];
    __shared__ float cse[KEFF], csi[KEFF], cnse[KEFF], cnsi[KEFF];
    int s   = blockIdx.y;
    int t0  = blockIdx.x * CONV_CHUNK;
    int tid = threadIdx.x;
    if (tid < KEFF) {
        cse[tid]  = g_ker[0][s][tid];
        csi[tid]  = g_ker[1][s][tid];
        cnse[tid] = g_ker[2][s][tid];
        cnsi[tid] = g_ker[3][s][tid];
    }
    for (int n = tid; n < CONV_CHUNK + KEFF; n += 256) {
        int t = t0 - KEFF + n;
        bool ok = (t >= 0) && (t < T_DATA);
        se_sm[n] = ok ? g_INe[s][t] : 0.f;
        si_sm[n] = ok ? g_INi[s][t] : 0.f;
    }
    __syncthreads();

    float as[4] = {0.f, 0.f, 0.f, 0.f};
    float an[4] = {0.f, 0.f, 0.f, 0.f};
#pragma unroll 4
    for (int k = 0; k < KEFF; k++) {
        float a = cse[k], b = csi[k], c = cnse[k], d = cnsi[k];
#pragma unroll
        for (int r = 0; r < 4; r++) {
            int idx = KEFF + tid + (r << 8) - k;
            float ve = se_sm[idx];
            float vi = si_sm[idx];
            as[r] = fmaf(a, ve, as[r]);
            as[r] = fmaf(b, vi, as[r]);
            an[r] = fmaf(c, ve, an[r]);
            an[r] = fmaf(d, vi, an[r]);
        }
    }
#pragma unroll
    for (int r = 0; r < 4; r++) {
        int t = t0 + tid + (r << 8);
        if (t < T_DATA) { g_syn_s[s][t] = as[r]; g_syn_ns[s][t] = an[r]; }
    }
}

// ---------------- kernel 4: level-parallel "scan" ----------------
// C_den is strictly lower triangular => subunit i at time t depends only on subunits j<i
// at time t-1. Dependence dies after <=11 time steps (level hits 0), so a 16-step halo
// makes every block exact. Levels exchanged via smem + __syncthreads.
#define SC_T 256
#define HALO 16
#define OUTB (SC_T - HALO)  // 240

__global__ void __launch_bounds__(SC_T, 1)
scan_kernel(const float* __restrict__ Cden, const float* __restrict__ Ths,
            const float* __restrict__ Thns, const float* __restrict__ Wss,
            const float* __restrict__ Wnsb, float* __restrict__ out) {
    __shared__ float Ysm_ns[SUBN][SC_T + 1];
    __shared__ float Ysm_s[SUBN][SC_T + 1];
    __shared__ float Cs[SUBN][SUBN];
    __shared__ float th_s[SUBN], th_ns[SUBN], w_s[SUBN], w_ns[SUBN];
    int tid = threadIdx.x;
    if (tid < 144) Cs[tid / 12][tid % 12] = Cden[tid];
    if (tid < SUBN) {
        th_s[tid]  = Ths[tid];
        th_ns[tid] = Thns[tid];
        w_s[tid]   = Wss[tid];
        w_ns[tid]  = Wnsb[tid];
        Ysm_ns[tid][0] = 0.f;   // Y(-1) = 0 slot
        Ysm_s[tid][0]  = 0.f;
    }
    long t = (long)blockIdx.x * OUTB - HALO + tid;
    bool vt = (t >= 0) && (t < T_DATA);
    int  tc = vt ? (int)t : 0;

    float sns[SUBN], ssy[SUBN];
#pragma unroll
    for (int i = 0; i < SUBN; i++) {
        sns[i] = vt ? g_syn_ns[i][tc] : 0.f;
        ssy[i] = vt ? g_syn_s[i][tc]  : 0.f;
    }
    __syncthreads();

    // ns chain: 12 levels
    float yp[SUBN], sg_ns[SUBN];
#pragma unroll
    for (int i = 0; i < SUBN; i++) {
        float x = sns[i] + th_ns[i];
#pragma unroll
        for (int j = 0; j < i; j++) x = fmaf(Cs[i][j], yp[j], x);
        float sg = sigm(x);
        sg_ns[i] = sg;
        Ysm_ns[i][tid + 1] = vt ? sg * w_ns[i] : 0.f;
        __syncthreads();
        yp[i] = Ysm_ns[i][tid];     // value at t-1
    }

    // Y_s at own t (root from s-chain, rest from ns sigmoids)
    float yso[SUBN];
    yso[0] = sigm(ssy[0] + th_s[0]) * w_s[0];
#pragma unroll
    for (int i = 1; i < SUBN; i++) yso[i] = sg_ns[i] * w_s[i];
#pragma unroll
    for (int i = 0; i < SUBN; i++) Ysm_s[i][tid + 1] = vt ? yso[i] : 0.f;
    __syncthreads();

    float ysp[SUBN];
#pragma unroll
    for (int i = 0; i < SUBN; i++) ysp[i] = Ysm_s[i][tid];  // Y_s at t-1

    if (tid >= HALO && t < T_DATA) {
        float* o = out + t * 35;
#pragma unroll
        for (int i = 0; i < SUBN; i++) {
            float x = ssy[i] + th_s[i];
#pragma unroll
            for (int j = 0; j < i; j++) x = fmaf(Cs[i][j], ysp[j], x);
            o[i]      = yso[i];             // Y_s(t)
            o[12 + i] = sg_ns[i] * w_ns[i]; // Y_ns(t)
            if (i >= 1) o[23 + i] = sigm(x); // sig_s[1:]
        }
    }
}

// ---------------- launch ----------------
extern "C" void kernel_launch(void* const* d_in, const int* in_sizes, int n_in,
                              void* d_out, int out_size) {
    const float* S_e     = (const float*)d_in[0];
    const float* S_i     = (const float*)d_in[1];
    const float* C_e     = (const float*)d_in[2];
    const float* C_i     = (const float*)d_in[3];
    const float* C_den   = (const float*)d_in[4];
    const float* W_s_syn = (const float*)d_in[5];
    const float* W_ns_syn= (const float*)d_in[6];
    const float* D_s     = (const float*)d_in[7];
    const float* D_ns    = (const float*)d_in[8];
    const float* Th_s    = (const float*)d_in[9];
    const float* Th_ns   = (const float*)d_in[10];
    const float* W_s_sub = (const float*)d_in[11];
    const float* W_ns_sub= (const float*)d_in[12];
    float* out = (float*)d_out;

    basis_kernel<<<(4 * SUBN * KEFF + 255) / 256, 256>>>(W_s_syn, W_ns_syn, D_s, D_ns);

    size_t smem = (size_t)(12 * 512 + 12 * 128) * sizeof(ulonglong2);  // 120 KB
    cudaFuncSetAttribute(gemm_kernel, cudaFuncAttributeMaxDynamicSharedMemorySize, (int)smem);
    gemm_kernel<<<148, 256, smem>>>((const ulonglong2*)S_e, (const ulonglong2*)S_i,
                                    (const ulonglong2*)C_e, (const ulonglong2*)C_i);

    dim3 cgrid((T_DATA + CONV_CHUNK - 1) / CONV_CHUNK, SUBN);
    conv_kernel<<<cgrid, 256>>>();

    int nsb = (T_DATA + OUTB - 1) / OUTB;
    scan_kernel<<<nsb, SC_T>>>(C_den, Th_s, Th_ns, W_s_sub, W_ns_sub, out);
}

// round 7
// speedup vs baseline: 1.1393x; 1.1393x over previous
#include <cuda_runtime.h>

#define T_DATA 20000
#define SUBN   12
#define KEFF   64          // kernel support truncation: tail < 1e-10 (tau_max = e ~ 2.72)

typedef unsigned long long u64;

// ---------------- device scratch (allocation-free rule: __device__ globals) ----------------
__device__ float g_INe[SUBN][T_DATA];       // S_e @ C_e.T, transposed [s][t]
__device__ float g_INi[SUBN][T_DATA];
__device__ float g_syn_s[SUBN][T_DATA];     // causal-conv outputs, [s][t]
__device__ float g_syn_ns[SUBN][T_DATA];

__device__ __forceinline__ float sigm(float x) {
    return __fdividef(1.0f, 1.0f + __expf(-x));
}

// packed 2xfp32 FMA (FFMA2) — PTX-only, pairs ride along the e-dimension for free
__device__ __forceinline__ u64 fma2(u64 a, u64 b, u64 acc) {
    asm("fma.rn.f32x2 %0, %1, %2, %0;" : "+l"(acc) : "l"(a), "l"(b));
    return acc;
}
__device__ __forceinline__ float f2sum(u64 v) {
    float lo = __uint_as_float((unsigned)(v & 0xffffffffull));
    float hi = __uint_as_float((unsigned)(v >> 32));
    return lo + hi;
}

// ---------------- kernel 1: skinny GEMM  IN[s][t] = sum_e S[t][e] * C[s][e] ----------------
// C staged in smem as 16B vectors (12x512 for E, 12x128 for I, zero padded).
// Warp owns 4 time rows; lanes sweep E in 16B slices with a one-slice register
// double-buffer (loads for sl+1 issued before computing sl -> MLP 8/warp).
#define TB 4
#define NTASK (T_DATA / TB)   // 5000

__global__ void __launch_bounds__(256, 1)
gemm_kernel(const ulonglong2* __restrict__ Se, const ulonglong2* __restrict__ Si,
            const ulonglong2* __restrict__ Ce, const ulonglong2* __restrict__ Ci) {
    extern __shared__ ulonglong2 sm4[];
    ulonglong2* Ce4 = sm4;            // [12][512]
    ulonglong2* Ci4 = sm4 + 12 * 512; // [12][128]
    int tid = threadIdx.x;
    for (int n = tid; n < 12 * 512; n += 256) {
        int s = n >> 9, q = n & 511;
        ulonglong2 v; v.x = 0ull; v.y = 0ull;
        if (q < 500) v = Ce[s * 500 + q];
        Ce4[n] = v;
    }
    for (int n = tid; n < 12 * 128; n += 256) {
        int s = n >> 7, q = n & 127;
        ulonglong2 v; v.x = 0ull; v.y = 0ull;
        if (q < 125) v = Ci[s * 125 + q];
        Ci4[n] = v;
    }
    __syncthreads();

    int lane = tid & 31;
    int gw   = blockIdx.x * 8 + (tid >> 5);
    int nw   = gridDim.x * 8;

    for (int task = gw; task < NTASK; task += nw) {
        int t0 = task * TB;
        u64 acc[TB][12];
        const ulonglong2* re = Se + (size_t)t0 * 500;   // 4 rows at +0,+500,+1000,+1500
        const ulonglong2* ri = Si + (size_t)t0 * 125;

        // ---------- phase E (16 slices, double-buffered) ----------
#pragma unroll
        for (int tb = 0; tb < TB; tb++)
#pragma unroll
            for (int s = 0; s < 12; s++) acc[tb][s] = 0ull;

        ulonglong2 av[TB];
#pragma unroll
        for (int tb = 0; tb < TB; tb++) av[tb] = re[tb * 500 + lane];  // slice 0 (lane<500 always)

#pragma unroll 1
        for (int sl = 0; sl < 16; sl++) {
            // prefetch slice sl+1 before computing sl
            ulonglong2 nv[TB];
            int e4n = ((sl + 1) << 5) + lane;
            bool okn = (sl < 15) && (e4n < 500);
#pragma unroll
            for (int tb = 0; tb < TB; tb++) {
                ulonglong2 v; v.x = 0ull; v.y = 0ull;
                if (okn) v = re[tb * 500 + e4n];
                nv[tb] = v;
            }
            int e4 = (sl << 5) + lane;
#pragma unroll
            for (int s = 0; s < 12; s++) {
                ulonglong2 c = Ce4[(s << 9) + e4];
#pragma unroll
                for (int tb = 0; tb < TB; tb++) {
                    u64 a = fma2(av[tb].x, c.x, acc[tb][s]);
                    acc[tb][s] = fma2(av[tb].y, c.y, a);
                }
            }
#pragma unroll
            for (int tb = 0; tb < TB; tb++) av[tb] = nv[tb];
        }
#pragma unroll
        for (int tb = 0; tb < TB; tb++)
#pragma unroll
            for (int s = 0; s < 12; s++) {
                float v = f2sum(acc[tb][s]);
                v += __shfl_xor_sync(0xffffffffu, v, 16);
                v += __shfl_xor_sync(0xffffffffu, v, 8);
                v += __shfl_xor_sync(0xffffffffu, v, 4);
                v += __shfl_xor_sync(0xffffffffu, v, 2);
                v += __shfl_xor_sync(0xffffffffu, v, 1);
                if (lane == s) g_INe[s][t0 + tb] = v;
            }

        // ---------- phase I (4 slices, double-buffered) ----------
#pragma unroll
        for (int tb = 0; tb < TB; tb++)
#pragma unroll
            for (int s = 0; s < 12; s++) acc[tb][s] = 0ull;

#pragma unroll
        for (int tb = 0; tb < TB; tb++) av[tb] = ri[tb * 125 + lane];  // slice 0 (lane<125 always)

#pragma unroll 1
        for (int sl = 0; sl < 4; sl++) {
            ulonglong2 nv[TB];
            int e4n = ((sl + 1) << 5) + lane;
            bool okn = (sl < 3) && (e4n < 125);
#pragma unroll
            for (int tb = 0; tb < TB; tb++) {
                ulonglong2 v; v.x = 0ull; v.y = 0ull;
                if (okn) v = ri[tb * 125 + e4n];
                nv[tb] = v;
            }
            int e4 = (sl << 5) + lane;
            bool ok = (e4 < 125);
#pragma unroll
            for (int tb = 0; tb < TB; tb++)
                if (!ok) { av[tb].x = 0ull; av[tb].y = 0ull; }
#pragma unroll
            for (int s = 0; s < 12; s++) {
                ulonglong2 c = Ci4[(s << 7) + e4];
#pragma unroll
                for (int tb = 0; tb < TB; tb++) {
                    u64 a = fma2(av[tb].x, c.x, acc[tb][s]);
                    acc[tb][s] = fma2(av[tb].y, c.y, a);
                }
            }
#pragma unroll
            for (int tb = 0; tb < TB; tb++) av[tb] = nv[tb];
        }
#pragma unroll
        for (int tb = 0; tb < TB; tb++)
#pragma unroll
            for (int s = 0; s < 12; s++) {
                float v = f2sum(acc[tb][s]);
                v += __shfl_xor_sync(0xffffffffu, v, 16);
                v += __shfl_xor_sync(0xffffffffu, v, 8);
                v += __shfl_xor_sync(0xffffffffu, v, 4);
                v += __shfl_xor_sync(0xffffffffu, v, 2);
                v += __shfl_xor_sync(0xffffffffu, v, 1);
                if (lane == s) g_INi[s][t0 + tb] = v;
            }
    }
}

// ---------------- kernel 2: causal conv, basis table fused in-block ----------------
#define CONV_CHUNK 1024
__global__ void __launch_bounds__(256)
conv_kernel(const float* __restrict__ Ws, const float* __restrict__ Wns,
            const float* __restrict__ Ds, const float* __restrict__ Dns) {
    __shared__ float se_sm[CONV_CHUNK + KEFF];
    __shared__ float si_sm[CONV_CHUNK + KEFF];
    __shared__ float ker[4][KEFF];   // 0: s_e  1: s_i  2: ns_e  3: ns_i
    int s   = blockIdx.y;
    int t0  = blockIdx.x * CONV_CHUNK;
    int tid = threadIdx.x;

    // fused basis: thread (q,k) computes one kernel tap for this subunit
    {
        int q = tid >> 6, k = tid & 63, c = q & 1;
        const float* W = (q >= 2) ? Wns : Ws;   // [12][3][2]
        const float* D = (q >= 2) ? Dns : Ds;   // [12][2]
        float d  = __expf(D[s * 2 + c]);
        float ts = fmaxf((float)k - d, 0.0f);
        float acc = 0.0f;
#pragma unroll
        for (int b = 0; b < 3; b++) {
            float tau = __expf(0.5f * (float)b);
            float tt  = ts / tau;
            acc += W[s * 6 + b * 2 + c] * tt * __expf(-tt);
        }
        ker[q][k] = acc;
    }
    for (int n = tid; n < CONV_CHUNK + KEFF; n += 256) {
        int t = t0 - KEFF + n;
        bool ok = (t >= 0) && (t < T_DATA);
        se_sm[n] = ok ? g_INe[s][t] : 0.f;
        si_sm[n] = ok ? g_INi[s][t] : 0.f;
    }
    __syncthreads();

    float as[4] = {0.f, 0.f, 0.f, 0.f};
    float an[4] = {0.f, 0.f, 0.f, 0.f};
#pragma unroll 4
    for (int k = 0; k < KEFF; k++) {
        float a = ker[0][k], b = ker[1][k], c = ker[2][k], d = ker[3][k];
#pragma unroll
        for (int r = 0; r < 4; r++) {
            int idx = KEFF + tid + (r << 8) - k;
            float ve = se_sm[idx];
            float vi = si_sm[idx];
            as[r] = fmaf(a, ve, as[r]);
            as[r] = fmaf(b, vi, as[r]);
            an[r] = fmaf(c, ve, an[r]);
            an[r] = fmaf(d, vi, an[r]);
        }
    }
#pragma unroll
    for (int r = 0; r < 4; r++) {
        int t = t0 + tid + (r << 8);
        if (t < T_DATA) { g_syn_s[s][t] = as[r]; g_syn_ns[s][t] = an[r]; }
    }
}

// ---------------- kernel 3: warp-autonomous shuffle scan ----------------
// C_den strictly lower triangular => total dependence depth <= 12 time steps
// (11 ns-chain levels + 1 for Y_s(t-1)). A warp covers 32 consecutive t with a
// 12-lane halo; level i is exact for lanes >= i, outputs (lanes 12..31) exact.
// No block barriers: level exchange via __shfl_up_sync.
#define SC_OUT 20   // outputs per warp (lanes 12..31)
__global__ void __launch_bounds__(128)
scan_kernel(const float* __restrict__ Cden, const float* __restrict__ Ths,
            const float* __restrict__ Thns, const float* __restrict__ Wss,
            const float* __restrict__ Wnsb, float* __restrict__ out) {
    __shared__ float Cs[SUBN][SUBN];
    __shared__ float th_s[SUBN], th_ns[SUBN], w_s[SUBN], w_ns[SUBN];
    int tid = threadIdx.x;
    for (int n = tid; n < 144; n += 128) Cs[n / 12][n % 12] = Cden[n];
    if (tid < SUBN) {
        th_s[tid]  = Ths[tid];
        th_ns[tid] = Thns[tid];
        w_s[tid]   = Wss[tid];
        w_ns[tid]  = Wnsb[tid];
    }
    __syncthreads();

    int lane = tid & 31;
    int wgid = blockIdx.x * 4 + (tid >> 5);
    int t    = wgid * SC_OUT + lane - 12;
    bool vt  = (t >= 0) && (t < T_DATA);
    int  tc  = vt ? t : 0;
    bool carry0 = (t <= 0);   // Y(t-1) = 0 at and before the sequence start

    float sns[SUBN], ssy[SUBN];
#pragma unroll
    for (int i = 0; i < SUBN; i++) {
        sns[i] = vt ? g_syn_ns[i][tc] : 0.f;
        ssy[i] = vt ? g_syn_s[i][tc]  : 0.f;
    }

    // ns chain: 12 levels, each exchanging its output with lane-1 (t-1)
    float ypm[SUBN], sg_ns[SUBN];
#pragma unroll
    for (int i = 0; i < SUBN; i++) {
        float x = sns[i] + th_ns[i];
#pragma unroll
        for (int j = 0; j < i; j++) x = fmaf(Cs[i][j], ypm[j], x);
        float sg = sigm(x);
        sg_ns[i] = sg;
        float y  = sg * w_ns[i];
        float ym = __shfl_up_sync(0xffffffffu, y, 1);
        ypm[i] = carry0 ? 0.f : ym;
    }

    // Y_s at own t (root from s-chain; C_den row 0 is zero)
    float yso[SUBN];
    yso[0] = sigm(ssy[0] + th_s[0]) * w_s[0];
#pragma unroll
    for (int i = 1; i < SUBN; i++) yso[i] = sg_ns[i] * w_s[i];

    float ysp[SUBN];
#pragma unroll
    for (int i = 0; i < SUBN; i++) {
        float v = __shfl_up_sync(0xffffffffu, yso[i], 1);
        ysp[i] = carry0 ? 0.f : v;
    }

    if (lane >= 12 && t < T_DATA) {
        float* o = out + (size_t)t * 35;
#pragma unroll
        for (int i = 0; i < SUBN; i++) {
            o[i]      = yso[i];             // Y_s(t)
            o[12 + i] = sg_ns[i] * w_ns[i]; // Y_ns(t)
        }
#pragma unroll
        for (int i = 1; i < SUBN; i++) {
            float x = ssy[i] + th_s[i];
#pragma unroll
            for (int j = 0; j < i; j++) x = fmaf(Cs[i][j], ysp[j], x);
            o[23 + i] = sigm(x);            // sig_s[1:]
        }
    }
}

// ---------------- launch ----------------
extern "C" void kernel_launch(void* const* d_in, const int* in_sizes, int n_in,
                              void* d_out, int out_size) {
    const float* S_e     = (const float*)d_in[0];
    const float* S_i     = (const float*)d_in[1];
    const float* C_e     = (const float*)d_in[2];
    const float* C_i     = (const float*)d_in[3];
    const float* C_den   = (const float*)d_in[4];
    const float* W_s_syn = (const float*)d_in[5];
    const float* W_ns_syn= (const float*)d_in[6];
    const float* D_s     = (const float*)d_in[7];
    const float* D_ns    = (const float*)d_in[8];
    const float* Th_s    = (const float*)d_in[9];
    const float* Th_ns   = (const float*)d_in[10];
    const float* W_s_sub = (const float*)d_in[11];
    const float* W_ns_sub= (const float*)d_in[12];
    float* out = (float*)d_out;

    size_t smem = (size_t)(12 * 512 + 12 * 128) * sizeof(ulonglong2);  // 120 KB
    cudaFuncSetAttribute(gemm_kernel, cudaFuncAttributeMaxDynamicSharedMemorySize, (int)smem);
    gemm_kernel<<<148, 256, smem>>>((const ulonglong2*)S_e, (const ulonglong2*)S_i,
                                    (const ulonglong2*)C_e, (const ulonglong2*)C_i);

    dim3 cgrid((T_DATA + CONV_CHUNK - 1) / CONV_CHUNK, SUBN);
    conv_kernel<<<cgrid, 256>>>(W_s_syn, W_ns_syn, D_s, D_ns);

    int nwarp = (T_DATA + SC_OUT - 1) / SC_OUT;       // 1000
    scan_kernel<<<(nwarp + 3) / 4, 128>>>(C_den, Th_s, Th_ns, W_s_sub, W_ns_sub, out);
}